// round 1
// baseline (speedup 1.0000x reference)
#include <cuda_runtime.h>
#include <cuda_bf16.h>
#include <stdint.h>

#define NB 4096
#define ND 256
#define NM 60
#define TILE 128
#define NT (NB / TILE)              // 32
#define NPAIR (NT * (NT + 1) / 2)   // 528

// Scratch (device globals: allocation-free per harness rules)
__device__ __nv_bfloat162 g_norm[NB * ND / 2];   // normalized reps, bf16, row-major [NB][ND]
__device__ uint4 g_mask[NB];                     // 128-bit code membership bitmask per row
__device__ int   g_cnt[NB];                      // popcount (unique code count) per row
__device__ float g_part[NPAIR * 4];              // per-block partials: neg_exp, pos_exp, pos_s, pos_cnt

// ---------------------------------------------------------------------------
// Fast exp: FMA-only (no MUFU, no CVT). rel err ~1.5e-7 on |s| <= ~11.
// exp(s) = 2^(s*log2e); round-to-nearest via magic constant; 2^f by deg-6 Taylor.
// ---------------------------------------------------------------------------
__device__ __forceinline__ float fexp(float s) {
    const float LOG2E = 1.4426950408889634f;
    const float MAGIC = 12582912.0f;             // 1.5 * 2^23
    float t  = s * LOG2E;
    float r  = fmaf(s, LOG2E, MAGIC);            // integer part lands in mantissa
    int   ei = __float_as_int(r) - 0x4B400000;   // extract round(t)
    float f  = t - (r - MAGIC);                  // f in [-0.5, 0.5]
    float z  = f * 0.6931471805599453f;          // f * ln2, |z| <= 0.3466
    float p  = fmaf(z, fmaf(z, fmaf(z, fmaf(z, fmaf(z,
                 fmaf(z, 1.3888889e-3f, 8.3333333e-3f),
                 4.1666668e-2f), 1.6666667e-1f), 0.5f), 1.0f), 1.0f);
    return __int_as_float(__float_as_int(p) + (ei << 23));
}

// ---------------------------------------------------------------------------
// Prep 1: normalize rows to bf16. One block per row, 128 threads, 2 elems each.
// ---------------------------------------------------------------------------
__global__ void k_norm(const float* __restrict__ rep) {
    int row = blockIdx.x;
    int t   = threadIdx.x;                        // 0..127
    const float2* rp = reinterpret_cast<const float2*>(rep + (size_t)row * ND);
    float2 x = rp[t];
    float ss = x.x * x.x + x.y * x.y;
    #pragma unroll
    for (int o = 16; o; o >>= 1) ss += __shfl_xor_sync(0xffffffffu, ss, o);
    __shared__ float sw[4];
    int w = t >> 5, l = t & 31;
    if (l == 0) sw[w] = ss;
    __syncthreads();
    float tot = sw[0] + sw[1] + sw[2] + sw[3];
    float inv = rsqrtf(tot);
    g_norm[(size_t)row * (ND / 2) + t] = __floats2bfloat162_rn(x.x * inv, x.y * inv);
}

// ---------------------------------------------------------------------------
// Prep 2: code bitmasks + counts. One thread per row.
// ---------------------------------------------------------------------------
__global__ void k_mask(const long long* __restrict__ codes) {
    int row = blockIdx.x * blockDim.x + threadIdx.x;
    if (row >= NB) return;
    const long long* mc = codes + (size_t)row * NM;
    uint32_t m0 = 0, m1 = 0, m2 = 0, m3 = 0;
    #pragma unroll
    for (int i = 0; i < NM; i++) {
        int c = (int)mc[i];                       // 0..99
        uint32_t b = 1u << (c & 31);
        int w = c >> 5;                           // 0..3
        if      (w == 0) m0 |= b;
        else if (w == 1) m1 |= b;
        else if (w == 2) m2 |= b;
        else             m3 |= b;
    }
    g_mask[row] = make_uint4(m0, m1, m2, m3);
    g_cnt[row]  = __popc(m0) + __popc(m1) + __popc(m2) + __popc(m3);
}

// ---------------------------------------------------------------------------
// Main pass: one block per upper-triangular 128x128 tile pair.
// 8 warps; warp w computes rows [w*16, w*16+16) x all 128 cols via mma.sync bf16.
// Epilogue fuses Jaccard mask, exp, and the 4 scalar accumulations.
// ---------------------------------------------------------------------------
#define PROC(ACC, MA, CA, MB, CB, EQ) do {                                   \
    int inter = __popc((MA).x & (MB).x) + __popc((MA).y & (MB).y) +          \
                __popc((MA).z & (MB).z) + __popc((MA).w & (MB).w);           \
    bool pos = (10 * inter > 3 * ((CA) + (CB) - inter)) && !(EQ);            \
    float s = (ACC) * 10.0f;                                                 \
    float e = fexp(s);                                                       \
    if (pos) { scnt++; sps += s; spe += e; } else { sneg += e; }             \
} while (0)

__global__ void __launch_bounds__(256) k_pair() {
    // decode blockIdx -> (ti, tj), ti <= tj
    int p = blockIdx.x;
    int ti = 0;
    while (p >= NT - ti) { p -= NT - ti; ti++; }
    int tj = ti + p;
    int i0 = ti * TILE, j0 = tj * TILE;
    bool diag = (ti == tj);

    __shared__ uint4 smA[TILE], smB[TILE];
    __shared__ int   scA[TILE], scB[TILE];
    __shared__ float red[8][4];

    int tid = threadIdx.x;
    if (tid < TILE) { smA[tid] = g_mask[i0 + tid]; scA[tid] = g_cnt[i0 + tid]; }
    else { int t2 = tid - TILE; smB[t2] = g_mask[j0 + t2]; scB[t2] = g_cnt[j0 + t2]; }

    int w = tid >> 5, lane = tid & 31;
    int g = lane >> 2, tg = lane & 3;

    const uint32_t* nrm = reinterpret_cast<const uint32_t*>(g_norm);
    const uint32_t* pA = nrm + (size_t)(i0 + w * 16 + g) * 128 + tg;
    const uint32_t* pB = nrm + (size_t)(j0 + g) * 128 + tg;

    float acc[64];
    #pragma unroll
    for (int i = 0; i < 64; i++) acc[i] = 0.0f;

    for (int kk = 0; kk < 16; kk++) {
        uint32_t a0 = pA[kk * 8];
        uint32_t a2 = pA[kk * 8 + 4];
        uint32_t a1 = pA[8 * 128 + kk * 8];
        uint32_t a3 = pA[8 * 128 + kk * 8 + 4];
        #pragma unroll
        for (int nt = 0; nt < 16; nt++) {
            uint32_t b0 = pB[nt * (8 * 128) + kk * 8];
            uint32_t b1 = pB[nt * (8 * 128) + kk * 8 + 4];
            float &c0 = acc[nt * 4 + 0];
            float &c1 = acc[nt * 4 + 1];
            float &c2 = acc[nt * 4 + 2];
            float &c3 = acc[nt * 4 + 3];
            asm volatile(
                "mma.sync.aligned.m16n8k16.row.col.f32.bf16.bf16.f32 "
                "{%0,%1,%2,%3}, {%4,%5,%6,%7}, {%8,%9}, {%0,%1,%2,%3};\n"
                : "+f"(c0), "+f"(c1), "+f"(c2), "+f"(c3)
                : "r"(a0), "r"(a1), "r"(a2), "r"(a3), "r"(b0), "r"(b1));
        }
    }

    __syncthreads();  // masks ready (loaded in parallel with nothing blocking above)

    // Epilogue: fragment (g, tg) mapping of m16n8k16 accumulators:
    //   c0 = C[g][tg*2], c1 = C[g][tg*2+1], c2 = C[g+8][tg*2], c3 = C[g+8][tg*2+1]
    int rl0 = w * 16 + g, rl1 = rl0 + 8;
    uint4 mA0 = smA[rl0]; int cA0 = scA[rl0];
    uint4 mA1 = smA[rl1]; int cA1 = scA[rl1];

    float sneg = 0.0f, spe = 0.0f, sps = 0.0f;
    int scnt = 0;

    #pragma unroll
    for (int nt = 0; nt < 16; nt++) {
        int c0 = nt * 8 + tg * 2;
        uint4 mB0 = smB[c0];     int cB0 = scB[c0];
        uint4 mB1 = smB[c0 + 1]; int cB1 = scB[c0 + 1];
        PROC(acc[nt * 4 + 0], mA0, cA0, mB0, cB0, diag && (rl0 == c0));
        PROC(acc[nt * 4 + 1], mA0, cA0, mB1, cB1, diag && (rl0 == c0 + 1));
        PROC(acc[nt * 4 + 2], mA1, cA1, mB0, cB0, diag && (rl1 == c0));
        PROC(acc[nt * 4 + 3], mA1, cA1, mB1, cB1, diag && (rl1 == c0 + 1));
    }

    // block reduce (deterministic, no atomics)
    float v0 = sneg, v1 = spe, v2 = sps, v3 = (float)scnt;
    #pragma unroll
    for (int o = 16; o; o >>= 1) {
        v0 += __shfl_xor_sync(0xffffffffu, v0, o);
        v1 += __shfl_xor_sync(0xffffffffu, v1, o);
        v2 += __shfl_xor_sync(0xffffffffu, v2, o);
        v3 += __shfl_xor_sync(0xffffffffu, v3, o);
    }
    if (lane == 0) { red[w][0] = v0; red[w][1] = v1; red[w][2] = v2; red[w][3] = v3; }
    __syncthreads();
    if (tid == 0) {
        float n = 0, pe = 0, ps = 0, pc = 0;
        #pragma unroll
        for (int i = 0; i < 8; i++) { n += red[i][0]; pe += red[i][1]; ps += red[i][2]; pc += red[i][3]; }
        float f = diag ? 1.0f : 2.0f;   // off-diagonal tiles represent (i,j) AND (j,i)
        g_part[blockIdx.x * 4 + 0] = n  * f;
        g_part[blockIdx.x * 4 + 1] = pe * f;
        g_part[blockIdx.x * 4 + 2] = ps * f;
        g_part[blockIdx.x * 4 + 3] = pc * f;
    }
}

// ---------------------------------------------------------------------------
// Final: deterministic double-precision reduction of 528 partials + loss.
// loss = log(negsum) + pos_exp/(negsum*n_pos) - pos_s/n_pos
// (log(e+N) = log N + log1p(e/N), e/N <= 2.2e-4 -> first order exact to ~2e-8)
// ---------------------------------------------------------------------------
__global__ void k_final(float* __restrict__ out) {
    int t = threadIdx.x;   // 256
    double n = 0, pe = 0, ps = 0, pc = 0;
    for (int p = t; p < NPAIR; p += 256) {
        n  += (double)g_part[p * 4 + 0];
        pe += (double)g_part[p * 4 + 1];
        ps += (double)g_part[p * 4 + 2];
        pc += (double)g_part[p * 4 + 3];
    }
    __shared__ double sd[4][256];
    sd[0][t] = n; sd[1][t] = pe; sd[2][t] = ps; sd[3][t] = pc;
    __syncthreads();
    for (int o = 128; o; o >>= 1) {
        if (t < o) {
            sd[0][t] += sd[0][t + o];
            sd[1][t] += sd[1][t + o];
            sd[2][t] += sd[2][t + o];
            sd[3][t] += sd[3][t + o];
        }
        __syncthreads();
    }
    if (t == 0) {
        double N = sd[0][0], PE = sd[1][0], PS = sd[2][0], PC = sd[3][0];
        double loss = 0.0;
        if (PC > 0.0) loss = log(N) + PE / (N * PC) - PS / PC;
        out[0] = (float)loss;
    }
}

extern "C" void kernel_launch(void* const* d_in, const int* in_sizes, int n_in,
                              void* d_out, int out_size) {
    (void)in_sizes; (void)n_in; (void)out_size;
    const float*     rep   = (const float*)d_in[0];
    const long long* codes = (const long long*)d_in[1];
    // d_in[2] = labels: unused by the reference loss

    k_norm<<<NB, 128>>>(rep);
    k_mask<<<(NB + 255) / 256, 256>>>(codes);
    k_pair<<<NPAIR, 256>>>();
    k_final<<<1, 256>>>((float*)d_out);
}

// round 5
// speedup vs baseline: 1.9582x; 1.9582x over previous
#include <cuda_runtime.h>
#include <cuda_fp16.h>
#include <stdint.h>

#define NB 4096
#define ND 256
#define NM 60
#define TILE 128
#define NT (NB / TILE)              // 32
#define NPAIR (NT * (NT + 1) / 2)   // 528
#define RSTRIDE 36                  // smem row stride in words (128B data + 16B pad)

// Device scratch (allocation-free). uint4-typed => 16B alignment for vector LDG.
__device__ uint4 g_norm4[NB * ND * 2 / 16];   // fp16 normalized reps, row-major [NB][ND]
__device__ uint4 g_mask[NB];                  // 128-bit code membership bitmask per row
__device__ int   g_cnt[NB];                   // unique-code count per row
__device__ float g_part[NPAIR * 4];           // per-block partials

// ---------------------------------------------------------------------------
// Fast exp: FMA-only. rel err ~1.5e-7 on |s| <= ~11.
// ---------------------------------------------------------------------------
__device__ __forceinline__ float fexp(float s) {
    const float LOG2E = 1.4426950408889634f;
    const float MAGIC = 12582912.0f;             // 1.5 * 2^23
    float t  = s * LOG2E;
    float r  = fmaf(s, LOG2E, MAGIC);
    int   ei = __float_as_int(r) - 0x4B400000;
    float f  = t - (r - MAGIC);
    float z  = f * 0.6931471805599453f;
    float p  = fmaf(z, fmaf(z, fmaf(z, fmaf(z, fmaf(z,
                 fmaf(z, 1.3888889e-3f, 8.3333333e-3f),
                 4.1666668e-2f), 1.6666667e-1f), 0.5f), 1.0f), 1.0f);
    return __int_as_float(__float_as_int(p) + (ei << 23));
}

// ---------------------------------------------------------------------------
// Prep 1 (R1-proven shape): normalize rows to fp16. One block per row.
// ---------------------------------------------------------------------------
__global__ void k_norm(const float* __restrict__ rep) {
    int row = blockIdx.x;
    int t   = threadIdx.x;                        // 0..127
    const float2* rp = reinterpret_cast<const float2*>(rep + (size_t)row * ND);
    float2 x = rp[t];
    float ss = x.x * x.x + x.y * x.y;
    #pragma unroll
    for (int o = 16; o; o >>= 1) ss += __shfl_xor_sync(0xffffffffu, ss, o);
    __shared__ float sw[4];
    int w = t >> 5, l = t & 31;
    if (l == 0) sw[w] = ss;
    __syncthreads();
    float tot = sw[0] + sw[1] + sw[2] + sw[3];
    float inv = rsqrtf(tot);
    __half2 h = __floats2half2_rn(x.x * inv, x.y * inv);
    reinterpret_cast<__half2*>(g_norm4)[(size_t)row * (ND / 2) + t] = h;
}

// ---------------------------------------------------------------------------
// Prep 2 (R1 verbatim): code bitmasks + counts. One thread per row.
// ---------------------------------------------------------------------------
__global__ void k_mask(const long long* __restrict__ codes) {
    int row = blockIdx.x * blockDim.x + threadIdx.x;
    if (row >= NB) return;
    const long long* mc = codes + (size_t)row * NM;
    uint32_t m0 = 0, m1 = 0, m2 = 0, m3 = 0;
    #pragma unroll
    for (int i = 0; i < NM; i++) {
        int c = (int)mc[i];                       // 0..99
        uint32_t b = 1u << (c & 31);
        int w = c >> 5;                           // 0..3
        if      (w == 0) m0 |= b;
        else if (w == 1) m1 |= b;
        else if (w == 2) m2 |= b;
        else             m3 |= b;
    }
    g_mask[row] = make_uint4(m0, m1, m2, m3);
    g_cnt[row]  = __popc(m0) + __popc(m1) + __popc(m2) + __popc(m3);
}

// ---------------------------------------------------------------------------
// mma helper (f16 in, f32 acc)
// ---------------------------------------------------------------------------
#define MMA4(D, A, B0, B1)                                                   \
    asm volatile("mma.sync.aligned.m16n8k16.row.col.f32.f16.f16.f32 "        \
                 "{%0,%1,%2,%3},{%4,%5,%6,%7},{%8,%9},{%0,%1,%2,%3};\n"      \
                 : "+f"((D)[0]), "+f"((D)[1]), "+f"((D)[2]), "+f"((D)[3])    \
                 : "r"((A)[0]), "r"((A)[1]), "r"((A)[2]), "r"((A)[3]),       \
                   "r"(B0), "r"(B1))

#define PROC(ACC, MA, CA, MB, CB, EQ) do {                                   \
    int inter = __popc((MA).x & (MB).x) + __popc((MA).y & (MB).y) +          \
                __popc((MA).z & (MB).z) + __popc((MA).w & (MB).w);           \
    bool pos = (10 * inter > 3 * ((CA) + (CB) - inter)) && !(EQ);            \
    float s = (ACC) * 10.0f;                                                 \
    float e = fexp(s);                                                       \
    if (pos) { scnt++; sps += s; spe += e; } else { sneg += e; }             \
} while (0)

// ---------------------------------------------------------------------------
// Main pass: one block per upper-triangular 128x128 tile pair.
// Static smem, plain LDG->STS staging (64-k chunks), plain LDS fragment
// assembly (conflict-free via stride-36-word padding), fp16 mma.
// 8 warps as 4(M)x2(N), warp tile 32x64.
// ---------------------------------------------------------------------------
__global__ void __launch_bounds__(256) k_pair() {
    __shared__ uint32_t sA[TILE * RSTRIDE];   // 18432 B
    __shared__ uint32_t sB[TILE * RSTRIDE];   // 18432 B
    __shared__ uint4 smMA[TILE], smMB[TILE];
    __shared__ int   scA[TILE], scB[TILE];
    __shared__ float red[32];

    int tid = threadIdx.x;

    // decode blockIdx -> (ti, tj), ti <= tj  (R1-proven)
    int p = blockIdx.x, ti = 0;
    while (p >= NT - ti) { p -= NT - ti; ti++; }
    int tj = ti + p;
    int i0 = ti * TILE, j0 = tj * TILE;
    bool diag = (ti == tj);

    if (tid < TILE) { smMA[tid] = g_mask[i0 + tid]; scA[tid] = g_cnt[i0 + tid]; }
    else { int q = tid - TILE; smMB[q] = g_mask[j0 + q]; scB[q] = g_cnt[j0 + q]; }

    int lane = tid & 31, w = tid >> 5;
    int wm = w & 3, wn = w >> 2;                 // warp grid: 4(M) x 2(N)
    int g = lane >> 2, tg = lane & 3;

    float acc[64];
    #pragma unroll
    for (int i = 0; i < 64; i++) acc[i] = 0.0f;

    // K = 256 elems = 4 chunks of 64 elems (8 uint4 per row per chunk)
    #pragma unroll 1
    for (int kc = 0; kc < 4; kc++) {
        __syncthreads();                         // previous compute done (and masks on kc==0)
        #pragma unroll
        for (int r = 0; r < 4; r++) {
            int idx = tid + r * 256;             // 0..1023
            int row = idx >> 3, seg = idx & 7;
            uint4 va = g_norm4[(size_t)(i0 + row) * 32 + kc * 8 + seg];
            uint4 vb = g_norm4[(size_t)(j0 + row) * 32 + kc * 8 + seg];
            *reinterpret_cast<uint4*>(&sA[row * RSTRIDE + seg * 4]) = va;
            *reinterpret_cast<uint4*>(&sB[row * RSTRIDE + seg * 4]) = vb;
        }
        __syncthreads();

        #pragma unroll
        for (int kk = 0; kk < 4; kk++) {         // 4 k16 slices per chunk
            uint32_t a[2][4];
            #pragma unroll
            for (int mi = 0; mi < 2; mi++) {
                int rb = (wm * 32 + mi * 16 + g) * RSTRIDE + kk * 8 + tg;
                a[mi][0] = sA[rb];
                a[mi][1] = sA[rb + 8 * RSTRIDE];
                a[mi][2] = sA[rb + 4];
                a[mi][3] = sA[rb + 8 * RSTRIDE + 4];
            }
            #pragma unroll
            for (int nt = 0; nt < 8; nt++) {
                int rb = (wn * 64 + nt * 8 + g) * RSTRIDE + kk * 8 + tg;
                uint32_t b0 = sB[rb];
                uint32_t b1 = sB[rb + 4];
                MMA4(acc + nt * 4,      a[0], b0, b1);
                MMA4(acc + 32 + nt * 4, a[1], b0, b1);
            }
        }
    }

    // ---- epilogue: fragment c0..c3 = C[g][2tg], C[g][2tg+1], C[g+8][..] ----
    float sneg = 0.0f, spe = 0.0f, sps = 0.0f;
    int scnt = 0;

    #pragma unroll
    for (int mi = 0; mi < 2; mi++) {
        int rl0 = wm * 32 + mi * 16 + g;
        uint4 mA0 = smMA[rl0];     int cA0 = scA[rl0];
        uint4 mA1 = smMA[rl0 + 8]; int cA1 = scA[rl0 + 8];
        #pragma unroll
        for (int nt = 0; nt < 8; nt++) {
            int cl = wn * 64 + nt * 8 + tg * 2;
            uint4 mB0 = smMB[cl];     int cB0 = scB[cl];
            uint4 mB1 = smMB[cl + 1]; int cB1 = scB[cl + 1];
            float* A4 = acc + mi * 32 + nt * 4;
            PROC(A4[0], mA0, cA0, mB0, cB0, diag && (rl0 == cl));
            PROC(A4[1], mA0, cA0, mB1, cB1, diag && (rl0 == cl + 1));
            PROC(A4[2], mA1, cA1, mB0, cB0, diag && (rl0 + 8 == cl));
            PROC(A4[3], mA1, cA1, mB1, cB1, diag && (rl0 + 8 == cl + 1));
        }
    }

    // block reduce (deterministic, no atomics)
    float v0 = sneg, v1 = spe, v2 = sps, v3 = (float)scnt;
    #pragma unroll
    for (int o = 16; o; o >>= 1) {
        v0 += __shfl_xor_sync(0xffffffffu, v0, o);
        v1 += __shfl_xor_sync(0xffffffffu, v1, o);
        v2 += __shfl_xor_sync(0xffffffffu, v2, o);
        v3 += __shfl_xor_sync(0xffffffffu, v3, o);
    }
    if (lane == 0) { red[w * 4 + 0] = v0; red[w * 4 + 1] = v1;
                     red[w * 4 + 2] = v2; red[w * 4 + 3] = v3; }
    __syncthreads();
    if (tid == 0) {
        float n = 0, pe = 0, ps = 0, pc = 0;
        #pragma unroll
        for (int i = 0; i < 8; i++) {
            n += red[i * 4 + 0]; pe += red[i * 4 + 1];
            ps += red[i * 4 + 2]; pc += red[i * 4 + 3];
        }
        float f = diag ? 1.0f : 2.0f;   // off-diag tiles stand for (i,j) and (j,i)
        g_part[blockIdx.x * 4 + 0] = n  * f;
        g_part[blockIdx.x * 4 + 1] = pe * f;
        g_part[blockIdx.x * 4 + 2] = ps * f;
        g_part[blockIdx.x * 4 + 3] = pc * f;
    }
}

// ---------------------------------------------------------------------------
// Final (R1 verbatim): deterministic double-precision reduction + loss.
// log(e+N) = log N + e/N to ~2e-8 (e/N <= 2.2e-4), so:
// loss = log(negsum) + pos_exp/(negsum*n_pos) - pos_s/n_pos
// ---------------------------------------------------------------------------
__global__ void k_final(float* __restrict__ out) {
    int t = threadIdx.x;   // 256
    double n = 0, pe = 0, ps = 0, pc = 0;
    for (int q = t; q < NPAIR; q += 256) {
        n  += (double)g_part[q * 4 + 0];
        pe += (double)g_part[q * 4 + 1];
        ps += (double)g_part[q * 4 + 2];
        pc += (double)g_part[q * 4 + 3];
    }
    __shared__ double sd[4][256];
    sd[0][t] = n; sd[1][t] = pe; sd[2][t] = ps; sd[3][t] = pc;
    __syncthreads();
    for (int o = 128; o; o >>= 1) {
        if (t < o) {
            sd[0][t] += sd[0][t + o];
            sd[1][t] += sd[1][t + o];
            sd[2][t] += sd[2][t + o];
            sd[3][t] += sd[3][t + o];
        }
        __syncthreads();
    }
    if (t == 0) {
        double N = sd[0][0], PE = sd[1][0], PS = sd[2][0], PC = sd[3][0];
        double loss = 0.0;
        if (PC > 0.0) loss = log(N) + PE / (N * PC) - PS / PC;
        out[0] = (float)loss;
    }
}

extern "C" void kernel_launch(void* const* d_in, const int* in_sizes, int n_in,
                              void* d_out, int out_size) {
    (void)in_sizes; (void)n_in; (void)out_size;
    const float*     rep   = (const float*)d_in[0];
    const long long* codes = (const long long*)d_in[1];
    // d_in[2] = labels: unused by the reference loss

    k_norm<<<NB, 128>>>(rep);
    k_mask<<<(NB + 255) / 256, 256>>>(codes);
    k_pair<<<NPAIR, 256>>>();
    k_final<<<1, 256>>>((float*)d_out);
}

// round 6
// speedup vs baseline: 2.0229x; 1.0331x over previous
#include <cuda_runtime.h>
#include <cuda_fp16.h>
#include <stdint.h>

#define NB 4096
#define ND 256
#define NM 60
#define TILE 128
#define NT (NB / TILE)              // 32
#define NPAIR (NT * (NT + 1) / 2)   // 528
#define RSTRIDE 36                  // smem row stride in words (128B data + 16B pad)

// Device scratch (allocation-free). uint4-typed => 16B alignment for vector LDG.
__device__ uint4  g_norm4[NB * ND * 2 / 16];  // fp16 normalized reps, row-major [NB][ND]
__device__ uint4  g_mask[NB];                 // 128-bit code membership bitmask per row
__device__ int    g_cnt[NB];                  // unique-code count per row
__device__ float4 g_part4[NPAIR];             // per-block partials (16B aligned)

// ---------------------------------------------------------------------------
// Fast exp: FMA-only. rel err ~1.5e-7 on |s| <= ~11.  (numerics: UNCHANGED)
// ---------------------------------------------------------------------------
__device__ __forceinline__ float fexp(float s) {
    const float LOG2E = 1.4426950408889634f;
    const float MAGIC = 12582912.0f;             // 1.5 * 2^23
    float t  = s * LOG2E;
    float r  = fmaf(s, LOG2E, MAGIC);
    int   ei = __float_as_int(r) - 0x4B400000;
    float f  = t - (r - MAGIC);
    float z  = f * 0.6931471805599453f;
    float p  = fmaf(z, fmaf(z, fmaf(z, fmaf(z, fmaf(z,
                 fmaf(z, 1.3888889e-3f, 8.3333333e-3f),
                 4.1666668e-2f), 1.6666667e-1f), 0.5f), 1.0f), 1.0f);
    return __int_as_float(__float_as_int(p) + (ei << 23));
}

// ---------------------------------------------------------------------------
// Prep (merged launch): blocks [0,NB) = normalize one row each (R5 k_norm
// body verbatim); blocks [NB, NB+32) = mask path, 128 rows each (R5 k_mask
// body verbatim). Both paths proven in R5 — only the dispatch is new.
// ---------------------------------------------------------------------------
__global__ void __launch_bounds__(128) k_prep(const float* __restrict__ rep,
                                              const long long* __restrict__ codes) {
    int b = blockIdx.x;
    int t = threadIdx.x;                          // 0..127
    if (b < NB) {
        // ---- norm path ----
        int row = b;
        const float2* rp = reinterpret_cast<const float2*>(rep + (size_t)row * ND);
        float2 x = rp[t];
        float ss = x.x * x.x + x.y * x.y;
        #pragma unroll
        for (int o = 16; o; o >>= 1) ss += __shfl_xor_sync(0xffffffffu, ss, o);
        __shared__ float sw[4];
        int w = t >> 5, l = t & 31;
        if (l == 0) sw[w] = ss;
        __syncthreads();
        float tot = sw[0] + sw[1] + sw[2] + sw[3];
        float inv = rsqrtf(tot);
        __half2 h = __floats2half2_rn(x.x * inv, x.y * inv);
        reinterpret_cast<__half2*>(g_norm4)[(size_t)row * (ND / 2) + t] = h;
    } else {
        // ---- mask path ----
        int row = (b - NB) * 128 + t;
        if (row >= NB) return;
        const long long* mc = codes + (size_t)row * NM;
        uint32_t m0 = 0, m1 = 0, m2 = 0, m3 = 0;
        #pragma unroll
        for (int i = 0; i < NM; i++) {
            int c = (int)mc[i];                   // 0..99
            uint32_t bmask = 1u << (c & 31);
            int w = c >> 5;                       // 0..3
            if      (w == 0) m0 |= bmask;
            else if (w == 1) m1 |= bmask;
            else if (w == 2) m2 |= bmask;
            else             m3 |= bmask;
        }
        g_mask[row] = make_uint4(m0, m1, m2, m3);
        g_cnt[row]  = __popc(m0) + __popc(m1) + __popc(m2) + __popc(m3);
    }
}

// ---------------------------------------------------------------------------
// mma helper (f16 in, f32 acc)
// ---------------------------------------------------------------------------
#define MMA4(D, A, B0, B1)                                                   \
    asm volatile("mma.sync.aligned.m16n8k16.row.col.f32.f16.f16.f32 "        \
                 "{%0,%1,%2,%3},{%4,%5,%6,%7},{%8,%9},{%0,%1,%2,%3};\n"      \
                 : "+f"((D)[0]), "+f"((D)[1]), "+f"((D)[2]), "+f"((D)[3])    \
                 : "r"((A)[0]), "r"((A)[1]), "r"((A)[2]), "r"((A)[3]),       \
                   "r"(B0), "r"(B1))

#define PROC(ACC, MA, CA, MB, CB, EQ) do {                                   \
    int inter = __popc((MA).x & (MB).x) + __popc((MA).y & (MB).y) +          \
                __popc((MA).z & (MB).z) + __popc((MA).w & (MB).w);           \
    bool pos = (10 * inter > 3 * ((CA) + (CB) - inter)) && !(EQ);            \
    float s = (ACC) * 10.0f;                                                 \
    float e = fexp(s);                                                       \
    if (pos) { scnt++; sps += s; spe += e; } else { sneg += e; }             \
} while (0)

// ---------------------------------------------------------------------------
// Main pass: one block per upper-triangular 128x128 tile pair.
// Identical algorithm to R5; __launch_bounds__(256,2) caps regs at 128 so
// TWO blocks co-reside per SM (R5 ran at 1) — staging latency and epilogue
// of one block overlap the MMA phase of the other.
// ---------------------------------------------------------------------------
__global__ void __launch_bounds__(256, 2) k_pair() {
    __shared__ uint32_t sA[TILE * RSTRIDE];   // 18432 B
    __shared__ uint32_t sB[TILE * RSTRIDE];   // 18432 B
    __shared__ uint4 smMA[TILE], smMB[TILE];
    __shared__ int   scA[TILE], scB[TILE];
    __shared__ float red[32];

    int tid = threadIdx.x;

    // decode blockIdx -> (ti, tj), ti <= tj
    int p = blockIdx.x, ti = 0;
    while (p >= NT - ti) { p -= NT - ti; ti++; }
    int tj = ti + p;
    int i0 = ti * TILE, j0 = tj * TILE;
    bool diag = (ti == tj);

    if (tid < TILE) { smMA[tid] = g_mask[i0 + tid]; scA[tid] = g_cnt[i0 + tid]; }
    else { int q = tid - TILE; smMB[q] = g_mask[j0 + q]; scB[q] = g_cnt[j0 + q]; }

    int lane = tid & 31, w = tid >> 5;
    int wm = w & 3, wn = w >> 2;                 // warp grid: 4(M) x 2(N)
    int g = lane >> 2, tg = lane & 3;

    float acc[64];
    #pragma unroll
    for (int i = 0; i < 64; i++) acc[i] = 0.0f;

    // K = 256 elems = 4 chunks of 64 elems (8 uint4 per row per chunk)
    #pragma unroll 1
    for (int kc = 0; kc < 4; kc++) {
        __syncthreads();                         // previous compute done (and masks on kc==0)
        #pragma unroll
        for (int r = 0; r < 4; r++) {
            int idx = tid + r * 256;             // 0..1023
            int row = idx >> 3, seg = idx & 7;
            uint4 va = g_norm4[(size_t)(i0 + row) * 32 + kc * 8 + seg];
            uint4 vb = g_norm4[(size_t)(j0 + row) * 32 + kc * 8 + seg];
            *reinterpret_cast<uint4*>(&sA[row * RSTRIDE + seg * 4]) = va;
            *reinterpret_cast<uint4*>(&sB[row * RSTRIDE + seg * 4]) = vb;
        }
        __syncthreads();

        #pragma unroll
        for (int kk = 0; kk < 4; kk++) {         // 4 k16 slices per chunk
            uint32_t a[2][4];
            #pragma unroll
            for (int mi = 0; mi < 2; mi++) {
                int rb = (wm * 32 + mi * 16 + g) * RSTRIDE + kk * 8 + tg;
                a[mi][0] = sA[rb];
                a[mi][1] = sA[rb + 8 * RSTRIDE];
                a[mi][2] = sA[rb + 4];
                a[mi][3] = sA[rb + 8 * RSTRIDE + 4];
            }
            #pragma unroll
            for (int nt = 0; nt < 8; nt++) {
                int rb = (wn * 64 + nt * 8 + g) * RSTRIDE + kk * 8 + tg;
                uint32_t b0 = sB[rb];
                uint32_t b1 = sB[rb + 4];
                MMA4(acc + nt * 4,      a[0], b0, b1);
                MMA4(acc + 32 + nt * 4, a[1], b0, b1);
            }
        }
    }

    // ---- epilogue: fragment c0..c3 = C[g][2tg], C[g][2tg+1], C[g+8][..] ----
    float sneg = 0.0f, spe = 0.0f, sps = 0.0f;
    int scnt = 0;

    #pragma unroll
    for (int mi = 0; mi < 2; mi++) {
        int rl0 = wm * 32 + mi * 16 + g;
        uint4 mA0 = smMA[rl0];     int cA0 = scA[rl0];
        uint4 mA1 = smMA[rl0 + 8]; int cA1 = scA[rl0 + 8];
        #pragma unroll
        for (int nt = 0; nt < 8; nt++) {
            int cl = wn * 64 + nt * 8 + tg * 2;
            uint4 mB0 = smMB[cl];     int cB0 = scB[cl];
            uint4 mB1 = smMB[cl + 1]; int cB1 = scB[cl + 1];
            float* A4 = acc + mi * 32 + nt * 4;
            PROC(A4[0], mA0, cA0, mB0, cB0, diag && (rl0 == cl));
            PROC(A4[1], mA0, cA0, mB1, cB1, diag && (rl0 == cl + 1));
            PROC(A4[2], mA1, cA1, mB0, cB0, diag && (rl0 + 8 == cl));
            PROC(A4[3], mA1, cA1, mB1, cB1, diag && (rl0 + 8 == cl + 1));
        }
    }

    // block reduce (deterministic, no atomics)
    float v0 = sneg, v1 = spe, v2 = sps, v3 = (float)scnt;
    #pragma unroll
    for (int o = 16; o; o >>= 1) {
        v0 += __shfl_xor_sync(0xffffffffu, v0, o);
        v1 += __shfl_xor_sync(0xffffffffu, v1, o);
        v2 += __shfl_xor_sync(0xffffffffu, v2, o);
        v3 += __shfl_xor_sync(0xffffffffu, v3, o);
    }
    if (lane == 0) { red[w * 4 + 0] = v0; red[w * 4 + 1] = v1;
                     red[w * 4 + 2] = v2; red[w * 4 + 3] = v3; }
    __syncthreads();
    if (tid == 0) {
        float n = 0, pe = 0, ps = 0, pc = 0;
        #pragma unroll
        for (int i = 0; i < 8; i++) {
            n += red[i * 4 + 0]; pe += red[i * 4 + 1];
            ps += red[i * 4 + 2]; pc += red[i * 4 + 3];
        }
        float f = diag ? 1.0f : 2.0f;   // off-diag tiles stand for (i,j) and (j,i)
        g_part4[blockIdx.x] = make_float4(n * f, pe * f, ps * f, pc * f);
    }
}

// ---------------------------------------------------------------------------
// Final: single warp, shfl-only deterministic double reduction + loss.
// loss = log(negsum) + pos_exp/(negsum*n_pos) - pos_s/n_pos
// ---------------------------------------------------------------------------
__global__ void k_final(float* __restrict__ out) {
    int t = threadIdx.x;   // 32
    double n = 0, pe = 0, ps = 0, pc = 0;
    for (int q = t; q < NPAIR; q += 32) {
        float4 v = g_part4[q];
        n += (double)v.x; pe += (double)v.y;
        ps += (double)v.z; pc += (double)v.w;
    }
    #pragma unroll
    for (int o = 16; o; o >>= 1) {
        n  += __shfl_xor_sync(0xffffffffu, n,  o);
        pe += __shfl_xor_sync(0xffffffffu, pe, o);
        ps += __shfl_xor_sync(0xffffffffu, ps, o);
        pc += __shfl_xor_sync(0xffffffffu, pc, o);
    }
    if (t == 0) {
        double loss = 0.0;
        if (pc > 0.0) loss = log(n) + pe / (n * pc) - ps / pc;
        out[0] = (float)loss;
    }
}

extern "C" void kernel_launch(void* const* d_in, const int* in_sizes, int n_in,
                              void* d_out, int out_size) {
    (void)in_sizes; (void)n_in; (void)out_size;
    const float*     rep   = (const float*)d_in[0];
    const long long* codes = (const long long*)d_in[1];
    // d_in[2] = labels: unused by the reference loss

    k_prep<<<NB + 32, 128>>>(rep, codes);
    k_pair<<<NPAIR, 256>>>();
    k_final<<<1, 32>>>((float*)d_out);
}

// round 7
// speedup vs baseline: 2.4411x; 1.2067x over previous
#include <cuda_runtime.h>
#include <cuda_fp16.h>
#include <stdint.h>

#define NB 4096
#define ND 256
#define NM 60
#define TILE 128
#define NT (NB / TILE)              // 32
#define NPAIR (NT * (NT + 1) / 2)   // 528
#define RSTRIDE 36                  // smem row stride in words (128B data + 16B pad)

// Device scratch (allocation-free). uint4-typed => 16B alignment for vector LDG.
__device__ uint4  g_norm4[NB * ND * 2 / 16];  // fp16 normalized reps, row-major [NB][ND]
__device__ uint4  g_mask[NB];                 // 128-bit code membership bitmask per row
__device__ int    g_cnt[NB];                  // unique-code count per row
__device__ float4 g_part4[NPAIR];             // per-block partials (16B aligned)

// ---------------------------------------------------------------------------
// Fast exp: FMA-only. rel err ~1.5e-7 on |s| <= ~11.  (numerics: UNCHANGED)
// ---------------------------------------------------------------------------
__device__ __forceinline__ float fexp(float s) {
    const float LOG2E = 1.4426950408889634f;
    const float MAGIC = 12582912.0f;             // 1.5 * 2^23
    float t  = s * LOG2E;
    float r  = fmaf(s, LOG2E, MAGIC);
    int   ei = __float_as_int(r) - 0x4B400000;
    float f  = t - (r - MAGIC);
    float z  = f * 0.6931471805599453f;
    float p  = fmaf(z, fmaf(z, fmaf(z, fmaf(z, fmaf(z,
                 fmaf(z, 1.3888889e-3f, 8.3333333e-3f),
                 4.1666668e-2f), 1.6666667e-1f), 0.5f), 1.0f), 1.0f);
    return __int_as_float(__float_as_int(p) + (ei << 23));
}

// ---------------------------------------------------------------------------
// Prep: WARP-PER-ROW. 8 warps/block, each warp fully owns one row:
//   norm:  2x float4 per lane (coalesced), shfl-reduce ss, 1x uint4 fp16 store
//   mask:  lanes read codes[lane], codes[32+lane]; shfl OR-reduce 128-bit mask
// No smem, no __syncthreads.
// ---------------------------------------------------------------------------
__global__ void __launch_bounds__(256) k_prep(const float* __restrict__ rep,
                                              const long long* __restrict__ codes) {
    int w    = threadIdx.x >> 5;                  // warp in block: 0..7
    int lane = threadIdx.x & 31;
    int row  = blockIdx.x * 8 + w;                // 512 blocks * 8 = 4096 rows

    // ---- norm path ----
    const float4* rp = reinterpret_cast<const float4*>(rep + (size_t)row * ND);
    float4 x0 = rp[lane * 2];
    float4 x1 = rp[lane * 2 + 1];
    float ss = x0.x * x0.x + x0.y * x0.y + x0.z * x0.z + x0.w * x0.w
             + x1.x * x1.x + x1.y * x1.y + x1.z * x1.z + x1.w * x1.w;
    #pragma unroll
    for (int o = 16; o; o >>= 1) ss += __shfl_xor_sync(0xffffffffu, ss, o);
    float inv = rsqrtf(ss);

    __half2 h[4];
    h[0] = __floats2half2_rn(x0.x * inv, x0.y * inv);
    h[1] = __floats2half2_rn(x0.z * inv, x0.w * inv);
    h[2] = __floats2half2_rn(x1.x * inv, x1.y * inv);
    h[3] = __floats2half2_rn(x1.z * inv, x1.w * inv);
    g_norm4[(size_t)row * 32 + lane] = *reinterpret_cast<uint4*>(h);

    // ---- mask path ----
    const long long* mc = codes + (size_t)row * NM;
    uint32_t m0 = 0, m1 = 0, m2 = 0, m3 = 0;
    {
        int c = (int)mc[lane];                    // lanes 0..31 read codes[0..31]
        uint32_t b = 1u << (c & 31);
        int wd = c >> 5;
        if      (wd == 0) m0 |= b;
        else if (wd == 1) m1 |= b;
        else if (wd == 2) m2 |= b;
        else              m3 |= b;
    }
    if (lane < NM - 32) {                         // lanes 0..27 read codes[32..59]
        int c = (int)mc[32 + lane];
        uint32_t b = 1u << (c & 31);
        int wd = c >> 5;
        if      (wd == 0) m0 |= b;
        else if (wd == 1) m1 |= b;
        else if (wd == 2) m2 |= b;
        else              m3 |= b;
    }
    #pragma unroll
    for (int o = 16; o; o >>= 1) {
        m0 |= __shfl_xor_sync(0xffffffffu, m0, o);
        m1 |= __shfl_xor_sync(0xffffffffu, m1, o);
        m2 |= __shfl_xor_sync(0xffffffffu, m2, o);
        m3 |= __shfl_xor_sync(0xffffffffu, m3, o);
    }
    if (lane == 0) {
        g_mask[row] = make_uint4(m0, m1, m2, m3);
        g_cnt[row]  = __popc(m0) + __popc(m1) + __popc(m2) + __popc(m3);
    }
}

// ---------------------------------------------------------------------------
// mma helper (f16 in, f32 acc)
// ---------------------------------------------------------------------------
#define MMA4(D, A, B0, B1)                                                   \
    asm volatile("mma.sync.aligned.m16n8k16.row.col.f32.f16.f16.f32 "        \
                 "{%0,%1,%2,%3},{%4,%5,%6,%7},{%8,%9},{%0,%1,%2,%3};\n"      \
                 : "+f"((D)[0]), "+f"((D)[1]), "+f"((D)[2]), "+f"((D)[3])    \
                 : "r"((A)[0]), "r"((A)[1]), "r"((A)[2]), "r"((A)[3]),       \
                   "r"(B0), "r"(B1))

#define PROC(ACC, MA, CA, MB, CB, EQ) do {                                   \
    int inter = __popc((MA).x & (MB).x) + __popc((MA).y & (MB).y) +          \
                __popc((MA).z & (MB).z) + __popc((MA).w & (MB).w);           \
    bool pos = (10 * inter > 3 * ((CA) + (CB) - inter)) && !(EQ);            \
    float s = (ACC) * 10.0f;                                                 \
    float e = fexp(s);                                                       \
    if (pos) { scnt++; sps += s; spe += e; } else { sneg += e; }             \
} while (0)

// ---------------------------------------------------------------------------
// Main pass (UNCHANGED from R6, passing): one block per upper-tri 128x128
// tile pair; static smem staging; fp16 mma; fused Jaccard/exp epilogue.
// ---------------------------------------------------------------------------
__global__ void __launch_bounds__(256, 2) k_pair() {
    __shared__ uint32_t sA[TILE * RSTRIDE];   // 18432 B
    __shared__ uint32_t sB[TILE * RSTRIDE];   // 18432 B
    __shared__ uint4 smMA[TILE], smMB[TILE];
    __shared__ int   scA[TILE], scB[TILE];
    __shared__ float red[32];

    int tid = threadIdx.x;

    // decode blockIdx -> (ti, tj), ti <= tj
    int p = blockIdx.x, ti = 0;
    while (p >= NT - ti) { p -= NT - ti; ti++; }
    int tj = ti + p;
    int i0 = ti * TILE, j0 = tj * TILE;
    bool diag = (ti == tj);

    if (tid < TILE) { smMA[tid] = g_mask[i0 + tid]; scA[tid] = g_cnt[i0 + tid]; }
    else { int q = tid - TILE; smMB[q] = g_mask[j0 + q]; scB[q] = g_cnt[j0 + q]; }

    int lane = tid & 31, w = tid >> 5;
    int wm = w & 3, wn = w >> 2;                 // warp grid: 4(M) x 2(N)
    int g = lane >> 2, tg = lane & 3;

    float acc[64];
    #pragma unroll
    for (int i = 0; i < 64; i++) acc[i] = 0.0f;

    // K = 256 elems = 4 chunks of 64 elems (8 uint4 per row per chunk)
    #pragma unroll 1
    for (int kc = 0; kc < 4; kc++) {
        __syncthreads();                         // previous compute done (and masks on kc==0)
        #pragma unroll
        for (int r = 0; r < 4; r++) {
            int idx = tid + r * 256;             // 0..1023
            int row = idx >> 3, seg = idx & 7;
            uint4 va = g_norm4[(size_t)(i0 + row) * 32 + kc * 8 + seg];
            uint4 vb = g_norm4[(size_t)(j0 + row) * 32 + kc * 8 + seg];
            *reinterpret_cast<uint4*>(&sA[row * RSTRIDE + seg * 4]) = va;
            *reinterpret_cast<uint4*>(&sB[row * RSTRIDE + seg * 4]) = vb;
        }
        __syncthreads();

        #pragma unroll
        for (int kk = 0; kk < 4; kk++) {         // 4 k16 slices per chunk
            uint32_t a[2][4];
            #pragma unroll
            for (int mi = 0; mi < 2; mi++) {
                int rb = (wm * 32 + mi * 16 + g) * RSTRIDE + kk * 8 + tg;
                a[mi][0] = sA[rb];
                a[mi][1] = sA[rb + 8 * RSTRIDE];
                a[mi][2] = sA[rb + 4];
                a[mi][3] = sA[rb + 8 * RSTRIDE + 4];
            }
            #pragma unroll
            for (int nt = 0; nt < 8; nt++) {
                int rb = (wn * 64 + nt * 8 + g) * RSTRIDE + kk * 8 + tg;
                uint32_t b0 = sB[rb];
                uint32_t b1 = sB[rb + 4];
                MMA4(acc + nt * 4,      a[0], b0, b1);
                MMA4(acc + 32 + nt * 4, a[1], b0, b1);
            }
        }
    }

    // ---- epilogue: fragment c0..c3 = C[g][2tg], C[g][2tg+1], C[g+8][..] ----
    float sneg = 0.0f, spe = 0.0f, sps = 0.0f;
    int scnt = 0;

    #pragma unroll
    for (int mi = 0; mi < 2; mi++) {
        int rl0 = wm * 32 + mi * 16 + g;
        uint4 mA0 = smMA[rl0];     int cA0 = scA[rl0];
        uint4 mA1 = smMA[rl0 + 8]; int cA1 = scA[rl0 + 8];
        #pragma unroll
        for (int nt = 0; nt < 8; nt++) {
            int cl = wn * 64 + nt * 8 + tg * 2;
            uint4 mB0 = smMB[cl];     int cB0 = scB[cl];
            uint4 mB1 = smMB[cl + 1]; int cB1 = scB[cl + 1];
            float* A4 = acc + mi * 32 + nt * 4;
            PROC(A4[0], mA0, cA0, mB0, cB0, diag && (rl0 == cl));
            PROC(A4[1], mA0, cA0, mB1, cB1, diag && (rl0 == cl + 1));
            PROC(A4[2], mA1, cA1, mB0, cB0, diag && (rl0 + 8 == cl));
            PROC(A4[3], mA1, cA1, mB1, cB1, diag && (rl0 + 8 == cl + 1));
        }
    }

    // block reduce (deterministic, no atomics)
    float v0 = sneg, v1 = spe, v2 = sps, v3 = (float)scnt;
    #pragma unroll
    for (int o = 16; o; o >>= 1) {
        v0 += __shfl_xor_sync(0xffffffffu, v0, o);
        v1 += __shfl_xor_sync(0xffffffffu, v1, o);
        v2 += __shfl_xor_sync(0xffffffffu, v2, o);
        v3 += __shfl_xor_sync(0xffffffffu, v3, o);
    }
    if (lane == 0) { red[w * 4 + 0] = v0; red[w * 4 + 1] = v1;
                     red[w * 4 + 2] = v2; red[w * 4 + 3] = v3; }
    __syncthreads();
    if (tid == 0) {
        float n = 0, pe = 0, ps = 0, pc = 0;
        #pragma unroll
        for (int i = 0; i < 8; i++) {
            n += red[i * 4 + 0]; pe += red[i * 4 + 1];
            ps += red[i * 4 + 2]; pc += red[i * 4 + 3];
        }
        float f = diag ? 1.0f : 2.0f;   // off-diag tiles stand for (i,j) and (j,i)
        g_part4[blockIdx.x] = make_float4(n * f, pe * f, ps * f, pc * f);
    }
}

// ---------------------------------------------------------------------------
// Final (UNCHANGED): single warp, shfl-only deterministic double reduction.
// loss = log(negsum) + pos_exp/(negsum*n_pos) - pos_s/n_pos
// ---------------------------------------------------------------------------
__global__ void k_final(float* __restrict__ out) {
    int t = threadIdx.x;   // 32
    double n = 0, pe = 0, ps = 0, pc = 0;
    for (int q = t; q < NPAIR; q += 32) {
        float4 v = g_part4[q];
        n += (double)v.x; pe += (double)v.y;
        ps += (double)v.z; pc += (double)v.w;
    }
    #pragma unroll
    for (int o = 16; o; o >>= 1) {
        n  += __shfl_xor_sync(0xffffffffu, n,  o);
        pe += __shfl_xor_sync(0xffffffffu, pe, o);
        ps += __shfl_xor_sync(0xffffffffu, ps, o);
        pc += __shfl_xor_sync(0xffffffffu, pc, o);
    }
    if (t == 0) {
        double loss = 0.0;
        if (pc > 0.0) loss = log(n) + pe / (n * pc) - ps / pc;
        out[0] = (float)loss;
    }
}

extern "C" void kernel_launch(void* const* d_in, const int* in_sizes, int n_in,
                              void* d_out, int out_size) {
    (void)in_sizes; (void)n_in; (void)out_size;
    const float*     rep   = (const float*)d_in[0];
    const long long* codes = (const long long*)d_in[1];
    // d_in[2] = labels: unused by the reference loss

    k_prep<<<NB / 8, 256>>>(rep, codes);
    k_pair<<<NPAIR, 256>>>();
    k_final<<<1, 32>>>((float*)d_out);
}